// round 1
// baseline (speedup 1.0000x reference)
#include <cuda_runtime.h>
#include <math.h>

#define NB      16
#define NPTS    4096
#define TILE    2048
#define P       4
#define THREADS 128
#define QCHUNKS (NPTS / (THREADS * P))   // 8
#define EPS     1e-6f
#define TOTAL_Q (NB * NPTS)              // 65536 queries per direction

// Scratch (no cudaMalloc allowed): packed points (x, y, z, ||p||^2)
// slot 0 = x tensor, slot 1 = y tensor
__device__ float4 g_packed[2][NB * NPTS];
__device__ float  g_acc;

// ---------------------------------------------------------------------------
// Pack kernel: (16,4096,3) fp32 -> float4 with squared norm in .w
// Also resets the accumulator (runs before the pass kernel in stream order).
// ---------------------------------------------------------------------------
__global__ void pack_kernel(const float* __restrict__ x,
                            const float* __restrict__ y) {
    int idx = blockIdx.x * blockDim.x + threadIdx.x;
    if (idx == 0) g_acc = 0.0f;
    if (idx >= NB * NPTS) return;

    const float* px = x + (size_t)idx * 3;
    const float* py = y + (size_t)idx * 3;

    float ax = px[0], ay = px[1], az = px[2];
    g_packed[0][idx] = make_float4(ax, ay, az, ax * ax + ay * ay + az * az);

    float bx = py[0], by = py[1], bz = py[2];
    g_packed[1][idx] = make_float4(bx, by, bz, bx * bx + by * by + bz * bz);
}

// ---------------------------------------------------------------------------
// Main pass: grid (QCHUNKS, NB, 2).
//   dir 0: queries = x (slot 0), candidates = y (slot 1)  -> min1
//   dir 1: queries = y (slot 1), candidates = x (slot 0)  -> min2
// Each thread owns P queries in registers; candidates stream through SMEM
// tiles as float4; inner loop per pair: 3-op dot + 1 FFMA + 1 FMNMX.
// sqrt/clamp deferred to after the min.
// ---------------------------------------------------------------------------
__global__ __launch_bounds__(THREADS, 8)
void chamfer_pass_kernel() {
    __shared__ float4 tile[TILE];

    const int dir = blockIdx.z;
    const int b   = blockIdx.y;
    const float4* __restrict__ Q = g_packed[dir]     + b * NPTS;
    const float4* __restrict__ C = g_packed[1 - dir] + b * NPTS;

    const int q0 = blockIdx.x * (THREADS * P) + threadIdx.x;

    float qx[P], qy[P], qz[P], q2[P], m[P];
#pragma unroll
    for (int p = 0; p < P; p++) {
        float4 q = Q[q0 + p * THREADS];
        qx[p] = q.x; qy[p] = q.y; qz[p] = q.z; q2[p] = q.w;
        m[p] = 3.4e38f;
    }

    for (int t = 0; t < NPTS; t += TILE) {
        __syncthreads();
#pragma unroll
        for (int j = threadIdx.x; j < TILE; j += THREADS)
            tile[j] = C[t + j];
        __syncthreads();

#pragma unroll 8
        for (int j = 0; j < TILE; j++) {
            float4 c = tile[j];
#pragma unroll
            for (int p = 0; p < P; p++) {
                float dot = fmaf(qx[p], c.x, fmaf(qy[p], c.y, qz[p] * c.z));
                float v   = fmaf(dot, -2.0f, c.w);   // c^2 - 2 q.c
                m[p] = fminf(m[p], v);
            }
        }
    }

    // Finish: dist = sqrt(eps + max(q2 + m, 0)), accumulate sum
    float local = 0.0f;
#pragma unroll
    for (int p = 0; p < P; p++) {
        float sq = fmaxf(q2[p] + m[p], 0.0f);
        local += sqrtf(EPS + sq);
    }

    // Block reduction (128 threads = 4 warps)
#pragma unroll
    for (int off = 16; off > 0; off >>= 1)
        local += __shfl_down_sync(0xFFFFFFFFu, local, off);

    __shared__ float warp_sums[THREADS / 32];
    int lane = threadIdx.x & 31;
    int wid  = threadIdx.x >> 5;
    if (lane == 0) warp_sums[wid] = local;
    __syncthreads();
    if (wid == 0) {
        float s = (lane < THREADS / 32) ? warp_sums[lane] : 0.0f;
#pragma unroll
        for (int off = 2; off > 0; off >>= 1)
            s += __shfl_down_sync(0xFFFFFFFFu, s, off);
        if (lane == 0) atomicAdd(&g_acc, s);
    }
}

// ---------------------------------------------------------------------------
// Finalize: result = (sum_min1 + sum_min2) / 65536
// ---------------------------------------------------------------------------
__global__ void finalize_kernel(float* __restrict__ out) {
    out[0] = g_acc * (1.0f / (float)TOTAL_Q);
}

extern "C" void kernel_launch(void* const* d_in, const int* in_sizes, int n_in,
                              void* d_out, int out_size) {
    const float* x = (const float*)d_in[0];
    const float* y = (const float*)d_in[1];
    float* out = (float*)d_out;

    pack_kernel<<<(NB * NPTS + 255) / 256, 256>>>(x, y);

    dim3 grid(QCHUNKS, NB, 2);
    chamfer_pass_kernel<<<grid, THREADS>>>();

    finalize_kernel<<<1, 1>>>(out);
}

// round 2
// speedup vs baseline: 1.0827x; 1.0827x over previous
#include <cuda_runtime.h>
#include <math.h>

#define NB      16
#define NPTS    4096
#define TILE    1024
#define P       4
#define THREADS 128
#define QCHUNKS (NPTS / (THREADS * P))   // 8
#define EPS     1e-6f
#define TOTAL_Q (NB * NPTS)              // 65536 queries per direction

// Scratch (no cudaMalloc allowed).
// g_cand: per candidate point, 2 float4s, components pre-scaled by -2 and
//         duplicated for f32x2 broadcast:
//         [2i+0] = (-2x, -2x, -2y, -2y)   [2i+1] = (-2z, -2z, n2, n2)
// g_query: (x, y, z, ||p||^2)
__device__ float4 g_cand [2][NB * NPTS * 2];
__device__ float4 g_query[2][NB * NPTS];
__device__ float  g_acc;

__device__ __forceinline__ unsigned long long pack2(float a, float b) {
    unsigned long long r;
    asm("mov.b64 %0, {%1, %2};" : "=l"(r) : "f"(a), "f"(b));
    return r;
}

// ---------------------------------------------------------------------------
// Pack kernel
// ---------------------------------------------------------------------------
__global__ void pack_kernel(const float* __restrict__ x,
                            const float* __restrict__ y) {
    int idx = blockIdx.x * blockDim.x + threadIdx.x;
    if (idx == 0) g_acc = 0.0f;
    if (idx >= NB * NPTS) return;

    {
        const float* p = x + (size_t)idx * 3;
        float a = p[0], b = p[1], c = p[2];
        float n2 = a * a + b * b + c * c;
        g_query[0][idx] = make_float4(a, b, c, n2);
        float sa = -2.0f * a, sb = -2.0f * b, sc = -2.0f * c;
        g_cand[0][2 * idx + 0] = make_float4(sa, sa, sb, sb);
        g_cand[0][2 * idx + 1] = make_float4(sc, sc, n2, n2);
    }
    {
        const float* p = y + (size_t)idx * 3;
        float a = p[0], b = p[1], c = p[2];
        float n2 = a * a + b * b + c * c;
        g_query[1][idx] = make_float4(a, b, c, n2);
        float sa = -2.0f * a, sb = -2.0f * b, sc = -2.0f * c;
        g_cand[1][2 * idx + 0] = make_float4(sa, sa, sb, sb);
        g_cand[1][2 * idx + 1] = make_float4(sc, sc, n2, n2);
    }
}

// ---------------------------------------------------------------------------
// Main pass: grid (QCHUNKS, NB, 2).
//   dir 0: queries = x, candidates = y  -> min1
//   dir 1: queries = y, candidates = x  -> min2
// Inner loop per candidate (4 queries = 2 f32x2 pairs):
//   2x LDS.128 + 6x FFMA2 + 4x FMNMX.  v = c2 - 2 q.c via prescaled chain;
//   sqrt/clamp/q2-add deferred past the min.
// ---------------------------------------------------------------------------
__global__ __launch_bounds__(THREADS, 8)
void chamfer_pass_kernel() {
    __shared__ float4 tile[TILE * 2];   // 32 KB

    const int dir = blockIdx.z;
    const int b   = blockIdx.y;
    const float4* __restrict__ Q = g_query[dir]     + b * NPTS;
    const float4* __restrict__ C = g_cand[1 - dir]  + (size_t)b * NPTS * 2;

    const int q0 = blockIdx.x * (THREADS * P) + threadIdx.x;

    float qx[P], qy[P], qz[P], q2[P];
#pragma unroll
    for (int p = 0; p < P; p++) {
        float4 q = Q[q0 + p * THREADS];
        qx[p] = q.x; qy[p] = q.y; qz[p] = q.z; q2[p] = q.w;
    }
    // Pack query pairs for f32x2
    unsigned long long qx01 = pack2(qx[0], qx[1]), qx23 = pack2(qx[2], qx[3]);
    unsigned long long qy01 = pack2(qy[0], qy[1]), qy23 = pack2(qy[2], qy[3]);
    unsigned long long qz01 = pack2(qz[0], qz[1]), qz23 = pack2(qz[2], qz[3]);

    float m0 = 3.4e38f, m1 = 3.4e38f, m2 = 3.4e38f, m3 = 3.4e38f;

    for (int t = 0; t < NPTS; t += TILE) {
        __syncthreads();
#pragma unroll
        for (int j = threadIdx.x; j < TILE * 2; j += THREADS)
            tile[j] = C[t * 2 + j];
        __syncthreads();

        const ulonglong2* tp = (const ulonglong2*)tile;
#pragma unroll 4
        for (int j = 0; j < TILE; j++) {
            ulonglong2 c0 = tp[2 * j + 0];   // .x=(cx,cx) .y=(cy,cy)  (prescaled -2)
            ulonglong2 c1 = tp[2 * j + 1];   // .x=(cz,cz) .y=(n2,n2)

            unsigned long long t01, t23;
            asm("fma.rn.f32x2 %0, %1, %2, %3;" : "=l"(t01) : "l"(qz01), "l"(c1.x), "l"(c1.y));
            asm("fma.rn.f32x2 %0, %1, %2, %3;" : "=l"(t23) : "l"(qz23), "l"(c1.x), "l"(c1.y));
            asm("fma.rn.f32x2 %0, %1, %2, %0;" : "+l"(t01) : "l"(qy01), "l"(c0.y));
            asm("fma.rn.f32x2 %0, %1, %2, %0;" : "+l"(t23) : "l"(qy23), "l"(c0.y));
            asm("fma.rn.f32x2 %0, %1, %2, %0;" : "+l"(t01) : "l"(qx01), "l"(c0.x));
            asm("fma.rn.f32x2 %0, %1, %2, %0;" : "+l"(t23) : "l"(qx23), "l"(c0.x));

            float v0, v1, v2, v3;
            asm("mov.b64 {%0, %1}, %2;" : "=f"(v0), "=f"(v1) : "l"(t01));
            asm("mov.b64 {%0, %1}, %2;" : "=f"(v2), "=f"(v3) : "l"(t23));
            m0 = fminf(m0, v0);
            m1 = fminf(m1, v1);
            m2 = fminf(m2, v2);
            m3 = fminf(m3, v3);
        }
    }

    // Finish: dist = sqrt(eps + max(q2 + m, 0)), accumulate
    float mm[P] = {m0, m1, m2, m3};
    float local = 0.0f;
#pragma unroll
    for (int p = 0; p < P; p++) {
        float sq = fmaxf(q2[p] + mm[p], 0.0f);
        local += sqrtf(EPS + sq);
    }

    // Block reduction (128 threads = 4 warps)
#pragma unroll
    for (int off = 16; off > 0; off >>= 1)
        local += __shfl_down_sync(0xFFFFFFFFu, local, off);

    __shared__ float warp_sums[THREADS / 32];
    int lane = threadIdx.x & 31;
    int wid  = threadIdx.x >> 5;
    if (lane == 0) warp_sums[wid] = local;
    __syncthreads();
    if (wid == 0) {
        float s = (lane < THREADS / 32) ? warp_sums[lane] : 0.0f;
#pragma unroll
        for (int off = 2; off > 0; off >>= 1)
            s += __shfl_down_sync(0xFFFFFFFFu, s, off);
        if (lane == 0) atomicAdd(&g_acc, s);
    }
}

// ---------------------------------------------------------------------------
__global__ void finalize_kernel(float* __restrict__ out) {
    out[0] = g_acc * (1.0f / (float)TOTAL_Q);
}

extern "C" void kernel_launch(void* const* d_in, const int* in_sizes, int n_in,
                              void* d_out, int out_size) {
    const float* x = (const float*)d_in[0];
    const float* y = (const float*)d_in[1];
    float* out = (float*)d_out;

    pack_kernel<<<(NB * NPTS + 255) / 256, 256>>>(x, y);

    dim3 grid(QCHUNKS, NB, 2);
    chamfer_pass_kernel<<<grid, THREADS>>>();

    finalize_kernel<<<1, 1>>>(out);
}

// round 3
// speedup vs baseline: 1.1550x; 1.0669x over previous
#include <cuda_runtime.h>
#include <math.h>

#define NB       16
#define NPTS     4096
#define C        16                       // candidates per thread (register-resident)
#define THREADS  128
#define CANDS_PER_BLOCK (THREADS * C)     // 2048
#define CCHUNKS  (NPTS / CANDS_PER_BLOCK) // 2
#define ROWSPLIT 32
#define ROWS_PER_BLOCK (NPTS / ROWSPLIT)  // 128
#define EPS      1e-6f
#define TOTAL_Q  (NB * NPTS)              // 65536

// Scratch (no cudaMalloc allowed)
__device__ float4   g_row[NB * NPTS];     // (yx, yy, yz, ||y||^2)
__device__ float4   g_col[NB * NPTS];     // (-2xx, -2xy, -2xz, ||x||^2)
__device__ unsigned g_rowmin[NB * NPTS];  // flipped-float bits, min over j of v
__device__ unsigned g_colmin[NB * NPTS];  // flipped-float bits, min over i of v

// Order-preserving float->uint transform (works for ALL floats incl. negatives):
// positive: set sign bit; negative: bitwise-not. Then uint compare == float compare.
__device__ __forceinline__ unsigned flipf(float f) {
    unsigned b = __float_as_uint(f);
    return b ^ (0x80000000u | (unsigned)((int)b >> 31));
}
__device__ __forceinline__ float unflipf(unsigned u) {
    unsigned b = (u & 0x80000000u) ? (u ^ 0x80000000u) : ~u;
    return __uint_as_float(b);
}

// ---------------------------------------------------------------------------
// Pack: build row/col point data, init min buffers to +inf (flipped = 0xFFFFFFFF),
// zero the output accumulator.
// ---------------------------------------------------------------------------
__global__ void pack_kernel(const float* __restrict__ x,
                            const float* __restrict__ y,
                            float* __restrict__ out) {
    int idx = blockIdx.x * blockDim.x + threadIdx.x;
    if (idx == 0) out[0] = 0.0f;
    if (idx >= NB * NPTS) return;

    const float* py = y + (size_t)idx * 3;
    float a = py[0], b = py[1], c = py[2];
    g_row[idx] = make_float4(a, b, c, a * a + b * b + c * c);

    const float* px = x + (size_t)idx * 3;
    float u = px[0], v = px[1], w = px[2];
    g_col[idx] = make_float4(-2.0f * u, -2.0f * v, -2.0f * w, u * u + v * v + w * w);

    g_rowmin[idx] = 0xFFFFFFFFu;
    g_colmin[idx] = 0xFFFFFFFFu;
}

// ---------------------------------------------------------------------------
// Fused pass: grid (CCHUNKS, ROWSPLIT, NB).
// Each thread holds C=16 candidates (cols = x points) + 16 colmin accumulators
// in registers. Block sweeps its 128-row slice (rows = y points) broadcast
// from smem. v[i,j] = y2_i + x2_j - 2 y_i.x_j computed ONCE, feeds both mins.
// ---------------------------------------------------------------------------
__global__ __launch_bounds__(THREADS, 4)
void chamfer_fused_kernel() {
    __shared__ float4 rowtile[ROWS_PER_BLOCK];   // 2 KB

    const int b  = blockIdx.z;
    const int rs = blockIdx.y;
    const int cc = blockIdx.x;

    const int row0 = rs * ROWS_PER_BLOCK;
    const int j0   = cc * CANDS_PER_BLOCK + threadIdx.x * C;

    const float4* __restrict__ R  = g_row + b * NPTS + row0;
    const float4* __restrict__ Cd = g_col + b * NPTS + j0;

    // Load candidates into registers
    float cx[C], cy[C], cz[C], cw[C], cm[C];
#pragma unroll
    for (int c = 0; c < C; c++) {
        float4 f = Cd[c];
        cx[c] = f.x; cy[c] = f.y; cz[c] = f.z; cw[c] = f.w;
        cm[c] = 3.4e38f;
    }

    // Load row slice into smem
    for (int i = threadIdx.x; i < ROWS_PER_BLOCK; i += THREADS)
        rowtile[i] = R[i];
    __syncthreads();

    const int lane = threadIdx.x & 31;

#pragma unroll 1
    for (int r = 0; r < ROWS_PER_BLOCK; r++) {
        float4 q = rowtile[r];   // broadcast LDS.128

        float s[C];
#pragma unroll
        for (int c = 0; c < C; c++) {
            float w = cw[c] + q.w;                                    // x2_j + y2_i
            float v = fmaf(q.x, cx[c], fmaf(q.y, cy[c], fmaf(q.z, cz[c], w)));
            cm[c] = fminf(cm[c], v);                                  // colmin (per-j)
            s[c] = v;
        }
        // Thread-local rowmin tree over 16 candidates (depth 4)
#pragma unroll
        for (int st = 1; st < C; st <<= 1)
#pragma unroll
            for (int k = 0; k < C; k += 2 * st)
                s[k] = fminf(s[k], s[k + st]);
        float rp = s[0];

        // Warp rowmin butterfly (covers 512 candidates)
#pragma unroll
        for (int o = 16; o > 0; o >>= 1)
            rp = fminf(rp, __shfl_xor_sync(0xFFFFFFFFu, rp, o));
        if (lane == 0)
            atomicMin(&g_rowmin[b * NPTS + row0 + r], flipf(rp));
    }

    // Flush partial colmins (this block's 128 rows)
#pragma unroll
    for (int c = 0; c < C; c++)
        atomicMin(&g_colmin[b * NPTS + j0 + c], flipf(cm[c]));
}

// ---------------------------------------------------------------------------
// Finalize: sum sqrt(eps + max(min, 0)) over both min sets, scale, accumulate.
// ---------------------------------------------------------------------------
__global__ void finalize_kernel(float* __restrict__ out) {
    int idx = blockIdx.x * blockDim.x + threadIdx.x;

    float local = 0.0f;
    if (idx < NB * NPTS) {
        float vr = unflipf(g_rowmin[idx]);   // min over j (per y point) -> min2
        float vc = unflipf(g_colmin[idx]);   // min over i (per x point) -> min1
        local  = sqrtf(EPS + fmaxf(vr, 0.0f));
        local += sqrtf(EPS + fmaxf(vc, 0.0f));
    }

#pragma unroll
    for (int o = 16; o > 0; o >>= 1)
        local += __shfl_down_sync(0xFFFFFFFFu, local, o);

    __shared__ float warp_sums[8];
    int lane = threadIdx.x & 31;
    int wid  = threadIdx.x >> 5;
    if (lane == 0) warp_sums[wid] = local;
    __syncthreads();
    if (wid == 0) {
        float sv = (lane < (int)(blockDim.x >> 5)) ? warp_sums[lane] : 0.0f;
#pragma unroll
        for (int o = 4; o > 0; o >>= 1)
            sv += __shfl_down_sync(0xFFFFFFFFu, sv, o);
        if (lane == 0) atomicAdd(out, sv * (1.0f / (float)TOTAL_Q));
    }
}

extern "C" void kernel_launch(void* const* d_in, const int* in_sizes, int n_in,
                              void* d_out, int out_size) {
    const float* x = (const float*)d_in[0];
    const float* y = (const float*)d_in[1];
    float* out = (float*)d_out;

    pack_kernel<<<(NB * NPTS + 255) / 256, 256>>>(x, y, out);

    dim3 grid(CCHUNKS, ROWSPLIT, NB);   // (2, 32, 16) = 1024 blocks
    chamfer_fused_kernel<<<grid, THREADS>>>();

    finalize_kernel<<<(NB * NPTS + 255) / 256, 256>>>(out);
}

// round 4
// speedup vs baseline: 1.3654x; 1.1821x over previous
#include <cuda_runtime.h>
#include <math.h>

#define NB       16
#define NPTS     4096
#define C        8                        // candidates per thread (register-resident)
#define THREADS  128
#define CANDS_PER_BLOCK (THREADS * C)     // 1024
#define CCHUNKS  (NPTS / CANDS_PER_BLOCK) // 4
#define ROWSPLIT 32
#define ROWS_PER_BLOCK (NPTS / ROWSPLIT)  // 128
#define RPAIRS   (ROWS_PER_BLOCK / 2)     // 64
#define EPS      1e-6f
#define TOTAL_Q  (NB * NPTS)

// Scratch (no cudaMalloc allowed)
// g_rowpair: per row pair (i0=2k, i1=2k+1), two float4s:
//   [2k+0] = (x_i0, x_i1, y_i0, y_i1)
//   [2k+1] = (z_i0, z_i1, w_i0, w_i1)   w = ||y_i||^2
// Reinterpreted as ulonglong2 -> 64-bit packed lanes for f32x2.
__device__ float4   g_rowpair[NB * NPTS];      // NPTS/2 pairs * 2 float4 per batch
__device__ float4   g_col[NB * NPTS];          // (-2x, -2y, -2z, ||x||^2)
__device__ unsigned g_rowmin[NB * NPTS];
__device__ unsigned g_colmin[NB * NPTS];

// Order-preserving float->uint (all floats incl. negatives)
__device__ __forceinline__ unsigned flipf(float f) {
    unsigned b = __float_as_uint(f);
    return b ^ (0x80000000u | (unsigned)((int)b >> 31));
}
__device__ __forceinline__ float unflipf(unsigned u) {
    unsigned b = (u & 0x80000000u) ? (u ^ 0x80000000u) : ~u;
    return __uint_as_float(b);
}

__device__ __forceinline__ unsigned long long pack2(float a, float b) {
    unsigned long long r;
    asm("mov.b64 %0, {%1, %2};" : "=l"(r) : "f"(a), "f"(b));
    return r;
}

// ---------------------------------------------------------------------------
// Pack kernel: one thread per row PAIR (handles 2 points of x and 2 of y).
// ---------------------------------------------------------------------------
__global__ void pack_kernel(const float* __restrict__ x,
                            const float* __restrict__ y,
                            float* __restrict__ out) {
    int k = blockIdx.x * blockDim.x + threadIdx.x;   // pair index
    if (k == 0) out[0] = 0.0f;
    if (k >= NB * NPTS / 2) return;

    int i0 = 2 * k, i1 = 2 * k + 1;

    // rows (y points)
    {
        const float* p0 = y + (size_t)i0 * 3;
        const float* p1 = y + (size_t)i1 * 3;
        float x0 = p0[0], y0 = p0[1], z0 = p0[2];
        float x1 = p1[0], y1 = p1[1], z1 = p1[2];
        float w0 = x0 * x0 + y0 * y0 + z0 * z0;
        float w1 = x1 * x1 + y1 * y1 + z1 * z1;
        g_rowpair[2 * k + 0] = make_float4(x0, x1, y0, y1);
        g_rowpair[2 * k + 1] = make_float4(z0, z1, w0, w1);
    }
    // cols (x points)
    {
        const float* p0 = x + (size_t)i0 * 3;
        const float* p1 = x + (size_t)i1 * 3;
        float a = p0[0], b = p0[1], c = p0[2];
        g_col[i0] = make_float4(-2.f * a, -2.f * b, -2.f * c, a * a + b * b + c * c);
        float u = p1[0], v = p1[1], w = p1[2];
        g_col[i1] = make_float4(-2.f * u, -2.f * v, -2.f * w, u * u + v * v + w * w);
    }
    g_rowmin[i0] = 0xFFFFFFFFu; g_rowmin[i1] = 0xFFFFFFFFu;
    g_colmin[i0] = 0xFFFFFFFFu; g_colmin[i1] = 0xFFFFFFFFu;
}

// ---------------------------------------------------------------------------
// Fused pass: grid (CCHUNKS, ROWSPLIT, NB) = (4, 32, 16) = 2048 blocks.
// Thread holds C=8 candidates, duplicated into 64-bit (c,c) registers once.
// Row pairs stream via broadcast LDS.128; v2 = (v_i0, v_i1) computed with
// 3x fma.rn.f32x2 + 1x add.rn.f32x2 per candidate -> 0.125 fma-cyc/pair.
// v feeds BOTH rowmin (per-row tree + warp butterfly) and colmin (register).
// ---------------------------------------------------------------------------
__global__ __launch_bounds__(THREADS, 4)
void chamfer_fused_kernel() {
    __shared__ float4 rowtile[RPAIRS * 2];   // 2 KB

    const int b  = blockIdx.z;
    const int rs = blockIdx.y;
    const int cc = blockIdx.x;

    const int row0 = rs * ROWS_PER_BLOCK;
    const int j0   = cc * CANDS_PER_BLOCK + threadIdx.x * C;

    const float4* __restrict__ RP = g_rowpair + b * NPTS + row0 * 2 / 2 * 2;  // b*NPTS + row0*2/... 
    // row pair storage: batch b starts at b*NPTS float4s; pair k of batch at +2k.
    // row0 is even; its pair index is row0/2 -> float4 offset row0.
    const float4* __restrict__ RPbase = g_rowpair + (size_t)b * NPTS + row0;
    const float4* __restrict__ Cd     = g_col     + (size_t)b * NPTS + j0;

    // Load candidates, duplicate into packed 64-bit registers
    unsigned long long cxd[C], cyd[C], czd[C], cwd[C];
    float cm[C];
#pragma unroll
    for (int c = 0; c < C; c++) {
        float4 f = Cd[c];
        cxd[c] = pack2(f.x, f.x);
        cyd[c] = pack2(f.y, f.y);
        czd[c] = pack2(f.z, f.z);
        cwd[c] = pack2(f.w, f.w);
        cm[c]  = 3.4e38f;
    }

    // Stage row slice
    for (int i = threadIdx.x; i < RPAIRS * 2; i += THREADS)
        rowtile[i] = RPbase[i];
    __syncthreads();

    const int lane = threadIdx.x & 31;
    const ulonglong2* tp = (const ulonglong2*)rowtile;

#pragma unroll 2
    for (int rp = 0; rp < RPAIRS; rp++) {
        ulonglong2 e0 = tp[2 * rp + 0];   // .x = xpair, .y = ypair
        ulonglong2 e1 = tp[2 * rp + 1];   // .x = zpair, .y = wpair (y2)

        float v0s[C], v1s[C];
#pragma unroll
        for (int c = 0; c < C; c++) {
            unsigned long long t;
            asm("fma.rn.f32x2 %0, %1, %2, %3;" : "=l"(t) : "l"(e1.x), "l"(czd[c]), "l"(cwd[c]));
            asm("fma.rn.f32x2 %0, %1, %2, %0;" : "+l"(t) : "l"(e0.y), "l"(cyd[c]));
            asm("fma.rn.f32x2 %0, %1, %2, %0;" : "+l"(t) : "l"(e0.x), "l"(cxd[c]));
            asm("add.rn.f32x2 %0, %0, %1;"     : "+l"(t) : "l"(e1.y));
            float v0, v1;
            asm("mov.b64 {%0, %1}, %2;" : "=f"(v0), "=f"(v1) : "l"(t));
            v0s[c] = v0; v1s[c] = v1;
            cm[c] = fminf(cm[c], fminf(v0, v1));          // colmin
        }

        // Row-min trees over C candidates (each row separately)
#pragma unroll
        for (int st = 1; st < C; st <<= 1)
#pragma unroll
            for (int k = 0; k < C; k += 2 * st) {
                v0s[k] = fminf(v0s[k], v0s[k + st]);
                v1s[k] = fminf(v1s[k], v1s[k + st]);
            }
        float r0 = v0s[0], r1 = v1s[0];

        // Warp butterflies (both rows together)
#pragma unroll
        for (int o = 16; o > 0; o >>= 1) {
            r0 = fminf(r0, __shfl_xor_sync(0xFFFFFFFFu, r0, o));
            r1 = fminf(r1, __shfl_xor_sync(0xFFFFFFFFu, r1, o));
        }
        if (lane == 0) {
            atomicMin(&g_rowmin[b * NPTS + row0 + 2 * rp + 0], flipf(r0));
            atomicMin(&g_rowmin[b * NPTS + row0 + 2 * rp + 1], flipf(r1));
        }
    }

    // Flush colmin partials
#pragma unroll
    for (int c = 0; c < C; c++)
        atomicMin(&g_colmin[b * NPTS + j0 + c], flipf(cm[c]));
}

// ---------------------------------------------------------------------------
__global__ void finalize_kernel(float* __restrict__ out) {
    int idx = blockIdx.x * blockDim.x + threadIdx.x;

    float local = 0.0f;
    if (idx < NB * NPTS) {
        float vr = unflipf(g_rowmin[idx]);
        float vc = unflipf(g_colmin[idx]);
        local  = sqrtf(EPS + fmaxf(vr, 0.0f));
        local += sqrtf(EPS + fmaxf(vc, 0.0f));
    }

#pragma unroll
    for (int o = 16; o > 0; o >>= 1)
        local += __shfl_down_sync(0xFFFFFFFFu, local, o);

    __shared__ float warp_sums[8];
    int lane = threadIdx.x & 31;
    int wid  = threadIdx.x >> 5;
    if (lane == 0) warp_sums[wid] = local;
    __syncthreads();
    if (wid == 0) {
        float sv = (lane < (int)(blockDim.x >> 5)) ? warp_sums[lane] : 0.0f;
#pragma unroll
        for (int o = 4; o > 0; o >>= 1)
            sv += __shfl_down_sync(0xFFFFFFFFu, sv, o);
        if (lane == 0) atomicAdd(out, sv * (1.0f / (float)TOTAL_Q));
    }
}

extern "C" void kernel_launch(void* const* d_in, const int* in_sizes, int n_in,
                              void* d_out, int out_size) {
    const float* x = (const float*)d_in[0];
    const float* y = (const float*)d_in[1];
    float* out = (float*)d_out;

    pack_kernel<<<(NB * NPTS / 2 + 255) / 256, 256>>>(x, y, out);

    dim3 grid(CCHUNKS, ROWSPLIT, NB);   // (4, 32, 16) = 2048 blocks
    chamfer_fused_kernel<<<grid, THREADS>>>();

    finalize_kernel<<<(NB * NPTS + 255) / 256, 256>>>(out);
}